// round 6
// baseline (speedup 1.0000x reference)
#include <cuda_runtime.h>
#include <math.h>

#define N_ANCH   8400
#define TOPK     10
#define ROI      3
#define NCHAN    256
#define FH       20
#define IOU_TH   0.45f
#define NT       256
#define CAND_MAX 1536
#define NBANDS   10
#define R_CAP    8          // register slots per lane; warp capacity 256
#define FULL     0xffffffffu

// ---------------------------------------------------------------------------
// One kernel, 90 blocks; each block redundantly runs banded greedy NMS, then
// emits its own (keep k, roi-point p) x 256-channel output slice.
//
// NMS equivalence (R2-R5 notes): descending-score greedy; bands partition
// scores downward from 0.99 and a lower band is materialized only when
// keeps < TOPK, so results never depend on unmaterialized lower scores.
// Selection order: max score, tie -> min original index (= jnp.argmax),
// encoded as (score_bits, negidx=0x7fffffff-idx) maximized lexicographically.
// Unique keys -> identical keep set in every block regardless of atomicAdd
// slot order.
//
// R6: redux.sync-based argmax (2 HW reductions + ballot + 4 shfl.idx instead
// of a 6-deep 64-bit shfl tree), 3-barrier fast path, cold multi-band ladder.
// ---------------------------------------------------------------------------
__global__ __launch_bounds__(NT) void fused_kernel(const float* __restrict__ pred,
                                                   const float* __restrict__ feat,
                                                   float* __restrict__ out)
{
    __shared__ unsigned long long c_key[CAND_MAX];
    __shared__ float4 c_box[CAND_MAX];
    __shared__ int    s_count, s_old, s_keeps;
    __shared__ float4 s_kbox[TOPK];

    const int tid  = threadIdx.x;
    const int lane = tid & 31;

    const float4* __restrict__ px4 = (const float4*)(pred);
    const float4* __restrict__ py4 = (const float4*)(pred + N_ANCH);
    const float4* __restrict__ pw4 = (const float4*)(pred + 2 * N_ANCH);
    const float4* __restrict__ ph4 = (const float4*)(pred + 3 * N_ANCH);
    const float4* __restrict__ pc4 = (const float4*)(pred + 4 * N_ANCH);

    if (tid == 0) { s_count = 0; s_keeps = 0; }
    __syncthreads();                                          // barrier 1

    // ---- band-0 compaction: conf >= 0.99, all 5 rows in one round trip ----
    for (int v = tid; v < N_ANCH / 4; v += NT) {
        float4 cf = pc4[v];
        float4 xx = px4[v], yy = py4[v], ww = pw4[v], hh = ph4[v];
        float cfa[4] = {cf.x, cf.y, cf.z, cf.w};
        float xa [4] = {xx.x, xx.y, xx.z, xx.w};
        float ya [4] = {yy.x, yy.y, yy.z, yy.w};
        float wa [4] = {ww.x, ww.y, ww.z, ww.w};
        float ha [4] = {hh.x, hh.y, hh.z, hh.w};
        #pragma unroll
        for (int j = 0; j < 4; j++) {
            float c = cfa[j];
            if (c >= 0.99f) {
                int slot = atomicAdd(&s_count, 1);
                if (slot < CAND_MAX) {
                    int a = v * 4 + j;
                    float wh = wa[j] * 0.5f, hh2 = ha[j] * 0.5f;
                    c_key[slot] = ((unsigned long long)__float_as_uint(c) << 32)
                                | (unsigned long long)(0x7fffffffu - (unsigned)a);
                    c_box[slot] = make_float4(xa[j] - wh, ya[j] - hh2,
                                              xa[j] + wh, ya[j] + hh2);
                }
            }
        }
    }
    __syncthreads();                                          // barrier 2

    // ---- warp 0: register-resident greedy NMS over band-0 pool ----
    if (tid < 32) {
        int count = min(s_count, CAND_MAX);
        int keeps = 0;

        if (count <= 32 * R_CAP) {
            unsigned sc[R_CAP], ni[R_CAP];
            float4   bx[R_CAP];
            #pragma unroll
            for (int r = 0; r < R_CAP; r++) {
                int j = r * 32 + lane;
                if (j < count) {
                    unsigned long long kk = c_key[j];
                    sc[r] = (unsigned)(kk >> 32);
                    ni[r] = (unsigned)kk;
                    bx[r] = c_box[j];
                } else { sc[r] = 0u; ni[r] = 0u; }
            }

            while (keeps < TOPK) {
                // local best (score, negidx, box) in fixed registers
                unsigned bs = 0u, bni = 0u; int bslot = -1;
                float4 bb = make_float4(0.f, 0.f, 0.f, 0.f);
                #pragma unroll
                for (int r = 0; r < R_CAP; r++) {
                    if (sc[r] > bs || (sc[r] == bs && ni[r] > bni)) {
                        bs = sc[r]; bni = ni[r]; bslot = r; bb = bx[r];
                    }
                }
                unsigned ws = __reduce_max_sync(FULL, bs);
                if (ws == 0u) break;                    // pool exhausted
                unsigned wni = __reduce_max_sync(FULL, (bs == ws) ? bni : 0u);
                bool win = (bs == ws) && (bni == wni);
                unsigned m = __ballot_sync(FULL, win);
                int wl = __ffs(m) - 1;

                float kx1 = __shfl_sync(FULL, bb.x, wl);
                float ky1 = __shfl_sync(FULL, bb.y, wl);
                float kx2 = __shfl_sync(FULL, bb.z, wl);
                float ky2 = __shfl_sync(FULL, bb.w, wl);
                if (win) s_kbox[keeps] = make_float4(kx1, ky1, kx2, ky2);

                float a1 = fmaxf(kx2 - kx1, 0.f) * fmaxf(ky2 - ky1, 0.f);
                #pragma unroll
                for (int r = 0; r < R_CAP; r++) {
                    if (sc[r] != 0u) {
                        float lx = fmaxf(kx1, bx[r].x), ly = fmaxf(ky1, bx[r].y);
                        float rx = fminf(kx2, bx[r].z), ry = fminf(ky2, bx[r].w);
                        float inter = fmaxf(rx - lx, 0.f) * fmaxf(ry - ly, 0.f);
                        float a2 = fmaxf(bx[r].z - bx[r].x, 0.f) * fmaxf(bx[r].w - bx[r].y, 0.f);
                        bool kill = (inter / fmaxf(a1 + a2 - inter, 1e-9f) > IOU_TH)
                                  || (win && r == bslot);
                        if (kill) { sc[r] = 0u; ni[r] = 0u; }
                    }
                }
                keeps++;
            }
            // write back kills so the (rare) ladder sees them
            if (keeps < TOPK) {
                #pragma unroll
                for (int r = 0; r < R_CAP; r++) {
                    int j = r * 32 + lane;
                    if (j < count)
                        c_key[j] = sc[r] ? (((unsigned long long)sc[r] << 32) | ni[r]) : 0ULL;
                }
            }
        } else {
            // oversized band-0 pool: smem loop (correct for any seed)
            while (keeps < TOPK) {
                unsigned long long bk = 0ULL; int bslot = 0;
                for (int j = lane; j < count; j += 32) {
                    unsigned long long kk = c_key[j];
                    if (kk > bk) { bk = kk; bslot = j; }
                }
                #pragma unroll
                for (int o = 16; o; o >>= 1) {
                    unsigned long long ok_ = __shfl_xor_sync(FULL, bk, o);
                    int                os_ = __shfl_xor_sync(FULL, bslot, o);
                    if (ok_ > bk) { bk = ok_; bslot = os_; }
                }
                if (bk == 0ULL) break;
                float4 bbx = c_box[bslot];
                if (lane == 0) s_kbox[keeps] = bbx;
                float a1 = fmaxf(bbx.z - bbx.x, 0.f) * fmaxf(bbx.w - bbx.y, 0.f);
                for (int j = lane; j < count; j += 32) {
                    if (c_key[j] == 0ULL) continue;
                    float4 b = c_box[j];
                    float lx = fmaxf(bbx.x, b.x), ly = fmaxf(bbx.y, b.y);
                    float rx = fminf(bbx.z, b.z), ry = fminf(bbx.w, b.w);
                    float inter = fmaxf(rx - lx, 0.f) * fmaxf(ry - ly, 0.f);
                    float a2 = fmaxf(b.z - b.x, 0.f) * fmaxf(b.w - b.y, 0.f);
                    if (inter / fmaxf(a1 + a2 - inter, 1e-9f) > IOU_TH) c_key[j] = 0ULL;
                }
                __syncwarp();
                keeps++;
            }
        }
        if (lane == 0) s_keeps = keeps;
    }
    __syncthreads();                                          // barrier 3

    // ---- cold path: descend bands until TOPK keeps or scores exhausted ----
    if (s_keeps < TOPK) {
        const float lo_tab[NBANDS] = {0.99f, 0.93f, 0.87f, 0.80f, 0.72f,
                                      0.64f, 0.55f, 0.45f, 0.35f, 0.25f};
        for (int band = 1; band < NBANDS; band++) {
            if (tid == 0) s_old = s_count;
            __syncthreads();
            const float lo = lo_tab[band], hi = lo_tab[band - 1];
            for (int v = tid; v < N_ANCH / 4; v += NT) {
                float4 cf = pc4[v];
                float4 xx = px4[v], yy = py4[v], ww = pw4[v], hh = ph4[v];
                float cfa[4] = {cf.x, cf.y, cf.z, cf.w};
                float xa [4] = {xx.x, xx.y, xx.z, xx.w};
                float ya [4] = {yy.x, yy.y, yy.z, yy.w};
                float wa [4] = {ww.x, ww.y, ww.z, ww.w};
                float ha [4] = {hh.x, hh.y, hh.z, hh.w};
                #pragma unroll
                for (int j = 0; j < 4; j++) {
                    float c = cfa[j];
                    if (c >= lo && c < hi) {
                        int slot = atomicAdd(&s_count, 1);
                        if (slot < CAND_MAX) {
                            int a = v * 4 + j;
                            float wh = wa[j] * 0.5f, hh2 = ha[j] * 0.5f;
                            c_key[slot] = ((unsigned long long)__float_as_uint(c) << 32)
                                        | (unsigned long long)(0x7fffffffu - (unsigned)a);
                            c_box[slot] = make_float4(xa[j] - wh, ya[j] - hh2,
                                                      xa[j] + wh, ya[j] + hh2);
                        }
                    }
                }
            }
            __syncthreads();

            if (tid < 32) {
                int count = min(s_count, CAND_MAX);
                int keeps = s_keeps;
                int nold  = s_old;
                // suppress new entries vs existing keeps
                for (int ki = 0; ki < keeps; ki++) {
                    float4 kb = s_kbox[ki];
                    float a1 = fmaxf(kb.z - kb.x, 0.f) * fmaxf(kb.w - kb.y, 0.f);
                    for (int j = nold + lane; j < count; j += 32) {
                        float4 b = c_box[j];
                        float lx = fmaxf(kb.x, b.x), ly = fmaxf(kb.y, b.y);
                        float rx = fminf(kb.z, b.z), ry = fminf(kb.w, b.w);
                        float inter = fmaxf(rx - lx, 0.f) * fmaxf(ry - ly, 0.f);
                        float a2 = fmaxf(b.z - b.x, 0.f) * fmaxf(b.w - b.y, 0.f);
                        if (inter / fmaxf(a1 + a2 - inter, 1e-9f) > IOU_TH) c_key[j] = 0ULL;
                    }
                }
                __syncwarp();
                while (keeps < TOPK) {
                    unsigned long long bk = 0ULL; int bslot = 0;
                    for (int j = lane; j < count; j += 32) {
                        unsigned long long kk = c_key[j];
                        if (kk > bk) { bk = kk; bslot = j; }
                    }
                    #pragma unroll
                    for (int o = 16; o; o >>= 1) {
                        unsigned long long ok_ = __shfl_xor_sync(FULL, bk, o);
                        int                os_ = __shfl_xor_sync(FULL, bslot, o);
                        if (ok_ > bk) { bk = ok_; bslot = os_; }
                    }
                    if (bk == 0ULL) break;
                    float4 bbx = c_box[bslot];
                    if (lane == 0) s_kbox[keeps] = bbx;
                    float a1 = fmaxf(bbx.z - bbx.x, 0.f) * fmaxf(bbx.w - bbx.y, 0.f);
                    for (int j = lane; j < count; j += 32) {
                        if (c_key[j] == 0ULL) continue;
                        float4 b = c_box[j];
                        float lx = fmaxf(bbx.x, b.x), ly = fmaxf(bbx.y, b.y);
                        float rx = fminf(bbx.z, b.z), ry = fminf(bbx.w, b.w);
                        float inter = fmaxf(rx - lx, 0.f) * fmaxf(ry - ly, 0.f);
                        float a2 = fmaxf(b.z - b.x, 0.f) * fmaxf(b.w - b.y, 0.f);
                        if (inter / fmaxf(a1 + a2 - inter, 1e-9f) > IOU_TH) c_key[j] = 0ULL;
                    }
                    __syncwarp();
                    keeps++;
                }
                if (lane == 0) s_keeps = keeps;
            }
            __syncthreads();
            if (s_keeps >= TOPK) break;
        }
    }

    // ---- ROI-align: this block's (k, p) slice ----
    const int b = blockIdx.x;
    const int k = b / (ROI * ROI);
    const int p = b - k * (ROI * ROI);
    const int c = tid;

    float* o = out + b * NCHAN + c;
    if (k >= s_keeps) { *o = 0.f; return; }

    const float scale = (float)FH / 640.0f;
    const float4 kb = s_kbox[k];
    const float sx1 = kb.x * scale, sy1 = kb.y * scale;
    const float sx2 = kb.z * scale, sy2 = kb.w * scale;
    const float bw = fmaxf(sx2 - sx1, 1e-6f) / (float)ROI;
    const float bh = fmaxf(sy2 - sy1, 1e-6f) / (float)ROI;

    const int gy = p / ROI;
    const int gx = p - gy * ROI;
    const float yg = sy1 + ((float)gy + 0.5f) * bh;
    const float xg = sx1 + ((float)gx + 0.5f) * bw;

    const float fy = floorf(yg), fx = floorf(xg);
    const float wy = yg - fy,    wx = xg - fx;

    int y0  = min(max((int)fy, 0), FH - 1);
    int x0  = min(max((int)fx, 0), FH - 1);
    int y1i = min(y0 + 1, FH - 1);
    int x1i = min(x0 + 1, FH - 1);

    const float* f = feat + c * (FH * FH);
    float v00 = f[y0  * FH + x0 ];
    float v01 = f[y0  * FH + x1i];
    float v10 = f[y1i * FH + x0 ];
    float v11 = f[y1i * FH + x1i];

    *o = v00 * (1.f - wy) * (1.f - wx)
       + v01 * (1.f - wy) * wx
       + v10 * wy * (1.f - wx)
       + v11 * wy * wx;
}

// ---------------------------------------------------------------------------
extern "C" void kernel_launch(void* const* d_in, const int* in_sizes, int n_in,
                              void* d_out, int out_size)
{
    const float* pred = (const float*)d_in[0];
    const float* feat = (const float*)d_in[1];
    if (n_in >= 2 && in_sizes[0] != 5 * N_ANCH) {   // defensive swap on sizes
        pred = (const float*)d_in[1];
        feat = (const float*)d_in[0];
    }
    float* out = (float*)d_out;

    fused_kernel<<<TOPK * ROI * ROI, NT>>>(pred, feat, out);
}